// round 10
// baseline (speedup 1.0000x reference)
#include <cuda_runtime.h>
#include <cuda_bf16.h>
#include <math.h>

// Problem constants (fixed by setup_inputs)
#define B   32
#define S   128
#define I_DIM 1024
#define H   1024
#define G   4096      // 4*H
#define V   32000
#define NB  128       // scan grid (H/8), all co-resident (< 148 SMs, 1 blk/SM)
#define BH  (B * H)

// ---------------------------------------------------------------------------
// Scratch (static __device__ arrays; no allocation allowed)
// ---------------------------------------------------------------------------
__device__ float d_xg[(size_t)S * B * G];             // precomputed input gates (S,B,4H)
__device__ float d_hs[(size_t)H * B * S];             // stored h, layout [n][s'*B+b]
__device__ int   d_rowids[S * B];                     // gather indices for embed GEMM
__device__ __nv_bfloat16 d_whi[(size_t)G * H];        // w_hh hi split (bf16)
__device__ __nv_bfloat16 d_wlo[(size_t)G * H];        // w_hh lo split (bf16)
__device__ __nv_bfloat16 d_hhi[2][BH];                // h hi split, [n][b], ping-pong
__device__ __nv_bfloat16 d_hlo[2][BH];                // h lo split, [n][b], ping-pong
__device__ unsigned g_arrive;                         // grid-barrier arrival counter

// ---------------------------------------------------------------------------
// Init: zero h0 splits, reset barrier, build gather row ids.
// ---------------------------------------------------------------------------
__global__ void init_kernel(const int* __restrict__ ids, int* __restrict__ rowids,
                            __nv_bfloat16* __restrict__ hhi,
                            __nv_bfloat16* __restrict__ hlo)
{
    int t = blockIdx.x * blockDim.x + threadIdx.x;
    if (t == 0) g_arrive = 0u;
    if (t < S * B) {
        int s = t >> 5;
        int b = t & 31;
        rowids[t] = ids[b * S + s];
    }
    if (t < BH) {
        hhi[t] = __float2bfloat16(0.f);
        hlo[t] = __float2bfloat16(0.f);
    }
}

// ---------------------------------------------------------------------------
// Split w_hh into bf16 hi/lo pair (hi + lo ~ fp32 to ~2^-17)
// ---------------------------------------------------------------------------
__global__ void wsplit_kernel(const float* __restrict__ w,
                              __nv_bfloat16* __restrict__ hi,
                              __nv_bfloat16* __restrict__ lo, int n)
{
    int i = blockIdx.x * blockDim.x + threadIdx.x;
    if (i < n) {
        float v = w[i];
        __nv_bfloat16 h = __float2bfloat16(v);
        hi[i] = h;
        lo[i] = __float2bfloat16(v - __bfloat162float(h));
    }
}

// ---------------------------------------------------------------------------
// mma / ldmatrix helpers
// ---------------------------------------------------------------------------
__device__ __forceinline__ unsigned f2tf(float f) {
    unsigned r;
    asm("cvt.rna.tf32.f32 %0, %1;" : "=r"(r) : "f"(f));
    return r;
}

#define MMA_TF32(d, a, b)                                                     \
    asm volatile(                                                             \
        "mma.sync.aligned.m16n8k8.row.col.f32.tf32.tf32.f32 "                 \
        "{%0,%1,%2,%3}, {%4,%5,%6,%7}, {%8,%9}, {%0,%1,%2,%3};\n"             \
        : "+f"(d[0]), "+f"(d[1]), "+f"(d[2]), "+f"(d[3])                      \
        : "r"(a[0]), "r"(a[1]), "r"(a[2]), "r"(a[3]), "r"(b[0]), "r"(b[1]))

#define MMA_BF16(d, a, b)                                                     \
    asm volatile(                                                             \
        "mma.sync.aligned.m16n8k16.row.col.f32.bf16.bf16.f32 "                \
        "{%0,%1,%2,%3}, {%4,%5,%6,%7}, {%8,%9}, {%0,%1,%2,%3};\n"             \
        : "+f"(d[0]), "+f"(d[1]), "+f"(d[2]), "+f"(d[3])                      \
        : "r"(a[0]), "r"(a[1]), "r"(a[2]), "r"(a[3]), "r"(b[0]), "r"(b[1]))

#define LDSM_X4T(r, addr)                                                     \
    asm volatile("ldmatrix.sync.aligned.m8n8.x4.trans.shared.b16 {%0,%1,%2,%3},[%4];" \
        : "=r"((r)[0]), "=r"((r)[1]), "=r"((r)[2]), "=r"((r)[3]) : "r"(addr))

#define LDSM_X2(r, addr)                                                      \
    asm volatile("ldmatrix.sync.aligned.m8n8.x2.shared.b16 {%0,%1},[%2];"     \
        : "=r"((r)[0]), "=r"((r)[1]) : "r"(addr))

// ---------------------------------------------------------------------------
// tf32 tensor-core GEMM, A row-major (+gather): C = A[row(m)] . Bm^T (+biases)
// ---------------------------------------------------------------------------
__global__ __launch_bounds__(256)
void gemm_tf32(const float* __restrict__ A, const float* __restrict__ Bm,
               const float* __restrict__ bias1, const float* __restrict__ bias2,
               float* __restrict__ C,
               int M, int N, int K,
               const int* __restrict__ arow)
{
    __shared__ unsigned As[128][20];
    __shared__ unsigned Bs[128][20];

    const int bm = blockIdx.y * 128;
    const int bn = blockIdx.x * 128;
    const int t    = threadIdx.x;
    const int lane = t & 31;
    const int w    = t >> 5;
    const int wm   = (w >> 2) * 64;
    const int wn   = (w & 3) * 32;
    const int gid  = lane >> 2;
    const int tk   = lane & 3;

    const int r0 = t >> 2;
    const int r1 = r0 + 64;
    const int kq = (t & 3) * 4;

    long ar0 = arow ? (long)arow[bm + r0] : (long)(bm + r0);
    long ar1 = arow ? (long)arow[bm + r1] : (long)(bm + r1);
    const float* Ap0 = A + ar0 * K + kq;
    const float* Ap1 = A + ar1 * K + kq;
    const float* Bp0 = Bm + (long)(bn + r0) * K + kq;
    const float* Bp1 = Bm + (long)(bn + r1) * K + kq;

    float acc[4][4][4];
    #pragma unroll
    for (int i = 0; i < 4; i++)
        #pragma unroll
        for (int j = 0; j < 4; j++)
            #pragma unroll
            for (int q = 0; q < 4; q++) acc[i][j][q] = 0.f;

    for (int k0 = 0; k0 < K; k0 += 16) {
        float4 va0 = *(const float4*)(Ap0 + k0);
        float4 va1 = *(const float4*)(Ap1 + k0);
        float4 vb0 = *(const float4*)(Bp0 + k0);
        float4 vb1 = *(const float4*)(Bp1 + k0);

        uint4 pa0 = make_uint4(f2tf(va0.x), f2tf(va0.y), f2tf(va0.z), f2tf(va0.w));
        uint4 pa1 = make_uint4(f2tf(va1.x), f2tf(va1.y), f2tf(va1.z), f2tf(va1.w));
        uint4 pb0 = make_uint4(f2tf(vb0.x), f2tf(vb0.y), f2tf(vb0.z), f2tf(vb0.w));
        uint4 pb1 = make_uint4(f2tf(vb1.x), f2tf(vb1.y), f2tf(vb1.z), f2tf(vb1.w));

        *(uint4*)&As[r0][kq] = pa0;
        *(uint4*)&As[r1][kq] = pa1;
        *(uint4*)&Bs[r0][kq] = pb0;
        *(uint4*)&Bs[r1][kq] = pb1;
        __syncthreads();

        #pragma unroll
        for (int ks = 0; ks < 16; ks += 8) {
            unsigned af[4][4], bf[4][2];
            #pragma unroll
            for (int i = 0; i < 4; i++) {
                int rb = wm + i * 16 + gid;
                af[i][0] = As[rb][ks + tk];
                af[i][1] = As[rb + 8][ks + tk];
                af[i][2] = As[rb][ks + tk + 4];
                af[i][3] = As[rb + 8][ks + tk + 4];
            }
            #pragma unroll
            for (int j = 0; j < 4; j++) {
                int nb = wn + j * 8 + gid;
                bf[j][0] = Bs[nb][ks + tk];
                bf[j][1] = Bs[nb][ks + tk + 4];
            }
            #pragma unroll
            for (int i = 0; i < 4; i++)
                #pragma unroll
                for (int j = 0; j < 4; j++)
                    MMA_TF32(acc[i][j], af[i], bf[j]);
        }
        __syncthreads();
    }

    #pragma unroll
    for (int i = 0; i < 4; i++) {
        int row = bm + wm + i * 16 + gid;
        #pragma unroll
        for (int j = 0; j < 4; j++) {
            int col = bn + wn + j * 8 + tk * 2;
            float b0v = 0.f, b1v = 0.f;
            if (bias1) { b0v += bias1[col]; b1v += bias1[col + 1]; }
            if (bias2) { b0v += bias2[col]; b1v += bias2[col + 1]; }
            float2 v0 = make_float2(acc[i][j][0] + b0v, acc[i][j][1] + b1v);
            float2 v1 = make_float2(acc[i][j][2] + b0v, acc[i][j][3] + b1v);
            *(float2*)&C[(long)row * N + col]       = v0;
            *(float2*)&C[(long)(row + 8) * N + col] = v1;
        }
    }
}

// ---------------------------------------------------------------------------
// tf32 GEMM, A COL-MAJOR ([K][M]) with output-row remap m=s'*B+b -> b*Sact+s'.
// A staging: contiguous STS.128 into As_cm[k][132]; frag reads conflict-free.
// ---------------------------------------------------------------------------
__global__ __launch_bounds__(256)
void gemm_tf32_cm(const float* __restrict__ A, const float* __restrict__ Bm,
                  const float* __restrict__ bias1,
                  float* __restrict__ C,
                  int M, int N, int K, int sact)
{
    __shared__ unsigned As[16][132];
    __shared__ unsigned Bs[128][20];

    const int bm = blockIdx.y * 128;
    const int bn = blockIdx.x * 128;
    const int t    = threadIdx.x;
    const int lane = t & 31;
    const int w    = t >> 5;
    const int wm   = (w >> 2) * 64;
    const int wn   = (w & 3) * 32;
    const int gid  = lane >> 2;
    const int tk   = lane & 3;

    // A staging: thread -> (k row = t>>5, 4 m's = (t&31)*4); 2 passes of 8 k.
    const int akr = t >> 5;            // 0..7
    const int amq = (t & 31) * 4;

    // B staging (row-major w_out): as in gemm_tf32
    const int r0 = t >> 2;
    const int r1 = r0 + 64;
    const int kq = (t & 3) * 4;
    const float* Bp0 = Bm + (long)(bn + r0) * K + kq;
    const float* Bp1 = Bm + (long)(bn + r1) * K + kq;

    float acc[4][4][4];
    #pragma unroll
    for (int i = 0; i < 4; i++)
        #pragma unroll
        for (int j = 0; j < 4; j++)
            #pragma unroll
            for (int q = 0; q < 4; q++) acc[i][j][q] = 0.f;

    for (int k0 = 0; k0 < K; k0 += 16) {
        #pragma unroll
        for (int p = 0; p < 2; p++) {
            int k = k0 + p * 8 + akr;
            float4 va = *(const float4*)(A + (long)k * M + bm + amq);
            uint4 pa = make_uint4(f2tf(va.x), f2tf(va.y), f2tf(va.z), f2tf(va.w));
            *(uint4*)&As[p * 8 + akr][amq] = pa;
        }
        float4 vb0 = *(const float4*)(Bp0 + k0);
        float4 vb1 = *(const float4*)(Bp1 + k0);
        uint4 pb0 = make_uint4(f2tf(vb0.x), f2tf(vb0.y), f2tf(vb0.z), f2tf(vb0.w));
        uint4 pb1 = make_uint4(f2tf(vb1.x), f2tf(vb1.y), f2tf(vb1.z), f2tf(vb1.w));
        *(uint4*)&Bs[r0][kq] = pb0;
        *(uint4*)&Bs[r1][kq] = pb1;
        __syncthreads();

        #pragma unroll
        for (int ks = 0; ks < 16; ks += 8) {
            unsigned af[4][4], bf[4][2];
            #pragma unroll
            for (int i = 0; i < 4; i++) {
                int rb = wm + i * 16 + gid;
                af[i][0] = As[ks + tk][rb];
                af[i][1] = As[ks + tk][rb + 8];
                af[i][2] = As[ks + tk + 4][rb];
                af[i][3] = As[ks + tk + 4][rb + 8];
            }
            #pragma unroll
            for (int j = 0; j < 4; j++) {
                int nb = wn + j * 8 + gid;
                bf[j][0] = Bs[nb][ks + tk];
                bf[j][1] = Bs[nb][ks + tk + 4];
            }
            #pragma unroll
            for (int i = 0; i < 4; i++)
                #pragma unroll
                for (int j = 0; j < 4; j++)
                    MMA_TF32(acc[i][j], af[i], bf[j]);
        }
        __syncthreads();
    }

    #pragma unroll
    for (int i = 0; i < 4; i++) {
        int mlin0 = bm + wm + i * 16 + gid;     // = s'*B + b
        int row0  = (mlin0 & 31) * sact + (mlin0 >> 5);
        int mlin1 = mlin0 + 8;
        int row1  = (mlin1 & 31) * sact + (mlin1 >> 5);
        #pragma unroll
        for (int j = 0; j < 4; j++) {
            int col = bn + wn + j * 8 + tk * 2;
            float b0v = bias1[col], b1v = bias1[col + 1];
            float2 v0 = make_float2(acc[i][j][0] + b0v, acc[i][j][1] + b1v);
            float2 v1 = make_float2(acc[i][j][2] + b0v, acc[i][j][3] + b1v);
            *(float2*)&C[(long)row0 * N + col] = v0;
            *(float2*)&C[(long)row1 * N + col] = v1;
        }
    }
}

// ---------------------------------------------------------------------------
// Persistent tensor-core LSTM scan (all 128 steps, W resident in SMEM).
// R9: h state in [n][b] layout (coalesced stores+loads, ldmatrix.trans A),
// 3 split-term accumulator chains (low reg pressure), red.release barrier.
// ---------------------------------------------------------------------------
#define KC 64
#define NCHUNK (H / KC)   // 16
#define WPITCH 36         // W row pitch, 32-bit words (conflict-free, as R8)
#define PB2 20            // h tile row pitch, words (40 bf16 = 80B)

#define SCAN_SMEM_BYTES ((2 * NCHUNK * 32 * WPITCH + 2 * 2 * KC * PB2) * 4 + 4 * 32 * 8 * 4)

__global__ __launch_bounds__(256, 1)
void lstm_scan(const float* __restrict__ xg_base,
               const __nv_bfloat16* __restrict__ whi,
               const __nv_bfloat16* __restrict__ wlo,
               __nv_bfloat16* __restrict__ hhi,   // [2][BH], [n][b]
               __nv_bfloat16* __restrict__ hlo,
               float* __restrict__ hs,            // [n][s'*B+b]
               int ctx, int Sact)
{
    extern __shared__ unsigned sm[];
    unsigned* wh  = sm;                            // [NCHUNK][32][WPITCH]
    unsigned* wl  = wh + NCHUNK * 32 * WPITCH;
    unsigned* shh = wl + NCHUNK * 32 * WPITCH;     // [2][KC][PB2]  h hi tile
    unsigned* shl = shh + 2 * KC * PB2;            // [2][KC][PB2]  h lo tile
    float* sgate  = (float*)(shl + 2 * KC * PB2);  // [4][32][8]

    const int t    = threadIdx.x;
    const int lane = t & 31;
    const int w    = t >> 5;
    const int wm   = (w >> 2) * 16;   // m-half base (0 or 16) — m = batch
    const int g    = w & 3;           // gate
    const int gid  = lane >> 2;
    const int tk   = lane & 3;
    const int n0   = blockIdx.x * 8;

    // ---- W staging (unchanged from R8, validated) ----
    const int sr   = t >> 3;
    const int sq   = (t & 7) * 4;
    const int wrow = (sr >> 3) * H + n0 + (sr & 7);
    const uint4* gWhi = (const uint4*)(whi + (long)wrow * H) + (t & 7);
    const uint4* gWlo = (const uint4*)(wlo + (long)wrow * H) + (t & 7);
    for (int ch = 0; ch < NCHUNK; ch++) {
        *(uint4*)&wh[(ch * 32 + sr) * WPITCH + sq] = gWhi[ch * 8];
        *(uint4*)&wl[(ch * 32 + sr) * WPITCH + sq] = gWlo[ch * 8];
    }

    // ---- h staging mapping: thread -> (k_local = t>>2, 8 b's = (t&3)*8) ----
    const int kl  = t >> 2;            // 0..63
    const int bq4 = (t & 3);           // uint4 index within 32-b row
    const unsigned h_sw = (unsigned)(kl * PB2 + bq4 * 4);   // smem word offset

    // ---- A-frag ldmatrix.trans addressing (h tile is [k][b], pitch 80B) ----
    const int a_kr = (lane & 7) + ((lane >> 4) & 1) * 8;   // k row within 16
    const int a_mc = wm + ((lane >> 3) & 1) * 8;           // b col
    const unsigned a_off = (unsigned)(a_kr * (PB2 * 4) + a_mc * 2);
    const unsigned HTILE_B = KC * PB2 * 4;                 // bytes per h tile buf

    // ---- B-frag addressing (unchanged from R8) ----
    const int b_row = g * 8 + (lane & 7);
    const int b_kh  = ((lane >> 3) & 1) * 4;
    const unsigned b_off = (unsigned)(b_row * WPITCH + b_kh) * 4;
    const unsigned WTILE_B = 32 * WPITCH * 4;

    const unsigned shh_base = (unsigned)__cvta_generic_to_shared(shh);
    const unsigned shl_base = (unsigned)__cvta_generic_to_shared(shl);
    const unsigned wh_base  = (unsigned)__cvta_generic_to_shared(wh);
    const unsigned wl_base  = (unsigned)__cvta_generic_to_shared(wl);

    const int b = t & 31;
    const int j = t >> 5;
    const int n = n0 + j;
    float cval  = 0.f;
    const float* xgp = xg_base + b * G + n;

    __syncthreads();

    for (int s = 0; s < S; s++) {
        const int pi = s & 1;
        const uint4* gHhi = (const uint4*)(hhi + (size_t)pi * BH) + kl * 4 + bq4;
        const uint4* gHlo = (const uint4*)(hlo + (size_t)pi * BH) + kl * 4 + bq4;

        // hoisted xg loads — hidden behind chunk loop
        const float* xgs = xgp + (size_t)s * (B * G);
        float xgi = __ldg(xgs);
        float xgf = __ldg(xgs + H);
        float xgg = __ldg(xgs + 2 * H);
        float xgo = __ldg(xgs + 3 * H);

        // prefetch chunks 0,1 (each chunk = 256 uint4 stride)
        uint4 rh[2], rl[2];
        rh[0] = __ldcg(gHhi);       rl[0] = __ldcg(gHlo);
        rh[1] = __ldcg(gHhi + 256); rl[1] = __ldcg(gHlo + 256);

        // 3 independent chains: hi*hi, lo*hi, hi*lo
        float aH[4] = {0.f,0.f,0.f,0.f};
        float aL[4] = {0.f,0.f,0.f,0.f};
        float aM[4] = {0.f,0.f,0.f,0.f};

        #pragma unroll 2
        for (int ch = 0; ch < NCHUNK; ch++) {
            const int buf = ch & 1;
            shh[buf * KC * PB2 + h_sw] = 0;  // (dead store eliminated below)
            *(uint4*)&shh[buf * KC * PB2 + h_sw] = rh[buf];
            *(uint4*)&shl[buf * KC * PB2 + h_sw] = rl[buf];
            __syncthreads();

            if (ch + 2 < NCHUNK) {
                rh[buf] = __ldcg(gHhi + (ch + 2) * 256);
                rl[buf] = __ldcg(gHlo + (ch + 2) * 256);
            }

            const unsigned sha = shh_base + buf * HTILE_B + a_off;
            const unsigned sla = shl_base + buf * HTILE_B + a_off;
            const unsigned whb = wh_base  + ch  * WTILE_B + b_off;
            const unsigned wlb = wl_base  + ch  * WTILE_B + b_off;

            #pragma unroll
            for (int ks = 0; ks < 4; ks++) {
                unsigned Ahi[4], Alo[4], Bhi[2], Blo[2];
                LDSM_X4T(Ahi, sha + ks * (16 * PB2 * 4));
                LDSM_X4T(Alo, sla + ks * (16 * PB2 * 4));
                LDSM_X2(Bhi, whb + ks * 32);
                LDSM_X2(Blo, wlb + ks * 32);
                MMA_BF16(aH, Ahi, Bhi);
                MMA_BF16(aL, Alo, Bhi);
                MMA_BF16(aM, Ahi, Blo);
            }
        }

        float fin[4];
        #pragma unroll
        for (int e = 0; e < 4; e++) fin[e] = aH[e] + (aL[e] + aM[e]);

        // gate exchange
        __syncthreads();
        sgate[(g * 32 + wm + gid) * 8 + 2 * tk]         = fin[0];
        sgate[(g * 32 + wm + gid) * 8 + 2 * tk + 1]     = fin[1];
        sgate[(g * 32 + wm + gid + 8) * 8 + 2 * tk]     = fin[2];
        sgate[(g * 32 + wm + gid + 8) * 8 + 2 * tk + 1] = fin[3];
        __syncthreads();

        // fused pointwise: thread = (b, j)
        float gi = sgate[(0 * 32 + b) * 8 + j] + xgi;
        float gf = sgate[(1 * 32 + b) * 8 + j] + xgf;
        float gg = sgate[(2 * 32 + b) * 8 + j] + xgg;
        float go = sgate[(3 * 32 + b) * 8 + j] + xgo;

        float iv = 1.f / (1.f + __expf(-gi));
        float fv = 1.f / (1.f + __expf(-gf));
        float gv = tanhf(gg);
        float ov = 1.f / (1.f + __expf(-go));

        cval = fv * cval + iv * gv;
        float hv = ov * tanhf(cval);

        // coalesced stores: h[n*32+b], hs[n][s'*B+b]
        const int po = (s + 1) & 1;
        const int hidx = n * B + b;
        __nv_bfloat16 hb = __float2bfloat16(hv);
        hhi[(size_t)po * BH + hidx] = hb;
        hlo[(size_t)po * BH + hidx] = __float2bfloat16(hv - __bfloat162float(hb));
        if (s >= ctx)
            hs[(long)n * (Sact * B) + (s - ctx) * B + b] = hv;

        if (s == S - 1) break;     // no barrier needed after last step

        // grid barrier: release-arrive (orders prior stores), acquire spin
        __syncthreads();
        if (t == 0) {
            asm volatile("red.release.gpu.global.add.u32 [%0], %1;"
                         :: "l"(&g_arrive), "r"(1u) : "memory");
            const unsigned bound = (unsigned)NB * (unsigned)(s + 1);
            unsigned v;
            do {
                asm volatile("ld.acquire.gpu.global.u32 %0, [%1];"
                             : "=r"(v) : "l"(&g_arrive) : "memory");
            } while (v < bound);
        }
        __syncthreads();
    }
}

// ---------------------------------------------------------------------------
// Launch
// ---------------------------------------------------------------------------
extern "C" void kernel_launch(void* const* d_in, const int* in_sizes, int n_in,
                              void* d_out, int out_size)
{
    const int*   ids   = (const int*)  d_in[0];
    const float* emb   = (const float*)d_in[1];
    const float* w_ih  = (const float*)d_in[2];
    const float* w_hh  = (const float*)d_in[3];
    const float* b_ih  = (const float*)d_in[4];
    const float* b_hh  = (const float*)d_in[5];
    const float* w_out = (const float*)d_in[6];
    const float* b_out = (const float*)d_in[7];

    int ctx  = S - (int)((long)out_size / ((long)B * V));   // = 40
    int Sact = S - ctx;                                     // = 88

    float* xg;   cudaGetSymbolAddress((void**)&xg,   d_xg);
    float* hs;   cudaGetSymbolAddress((void**)&hs,   d_hs);
    int* rowids; cudaGetSymbolAddress((void**)&rowids, d_rowids);
    __nv_bfloat16* whi; cudaGetSymbolAddress((void**)&whi, d_whi);
    __nv_bfloat16* wlo; cudaGetSymbolAddress((void**)&wlo, d_wlo);
    __nv_bfloat16* hhi; cudaGetSymbolAddress((void**)&hhi, d_hhi);
    __nv_bfloat16* hlo; cudaGetSymbolAddress((void**)&hlo, d_hlo);

    static bool attr_set = false;
    if (!attr_set) {
        cudaFuncSetAttribute(lstm_scan, cudaFuncAttributeMaxDynamicSharedMemorySize,
                             SCAN_SMEM_BYTES);
        attr_set = true;
    }

    // 1) init h0 / barrier / gather ids; split w_hh into bf16 hi/lo
    init_kernel<<<(BH + 255) / 256, 256>>>(ids, rowids, hhi, hlo);
    wsplit_kernel<<<(G * H + 255) / 256, 256>>>(w_hh, whi, wlo, G * H);

    // 2) x_gates = gather(emb, ids) @ w_ih^T + b_ih + b_hh   (tf32)
    gemm_tf32<<<dim3(G / 128, (S * B) / 128), 256>>>(
        emb, w_ih, b_ih, b_hh, xg, S * B, G, I_DIM, rowids);

    // 3) persistent scan: all 128 steps, W resident in SMEM
    lstm_scan<<<NB, 256, SCAN_SMEM_BYTES>>>(xg, whi, wlo, hhi, hlo, hs, ctx, Sact);

    // 4) logits = hs^T(col-major A) @ w_out^T + b_out, rows remapped
    gemm_tf32_cm<<<dim3(V / 128, (B * Sact) / 128), 256>>>(
        hs, w_out, b_out, (float*)d_out, B * Sact, V, H, Sact);
}

// round 13
// speedup vs baseline: 1.0226x; 1.0226x over previous
#include <cuda_runtime.h>
#include <cuda_bf16.h>
#include <math.h>

// Problem constants (fixed by setup_inputs)
#define B   32
#define S   128
#define I_DIM 1024
#define H   1024
#define G   4096      // 4*H
#define V   32000
#define NB  128       // scan grid (H/8), all co-resident (< 148 SMs, 1 blk/SM)
#define BH  (B * H)

// ---------------------------------------------------------------------------
// Scratch (static __device__ arrays; no allocation allowed)
// ---------------------------------------------------------------------------
__device__ float d_xg[(size_t)S * B * G];             // precomputed input gates (S,B,4H)
__device__ float d_hs[(size_t)H * B * S];             // stored h, layout [n][s'*B+b]
__device__ int   d_rowids[S * B];                     // gather indices for embed GEMM
__device__ __nv_bfloat16 d_whi[(size_t)G * H];        // w_hh hi split (bf16)
__device__ __nv_bfloat16 d_wlo[(size_t)G * H];        // w_hh lo split (bf16)
__device__ __nv_bfloat16 d_hhi[2][BH];                // h hi split, [n][b], ping-pong
__device__ __nv_bfloat16 d_hlo[2][BH];                // h lo split, [n][b], ping-pong
__device__ unsigned g_arrive;                         // grid-barrier arrival counter

// ---------------------------------------------------------------------------
// Init
// ---------------------------------------------------------------------------
__global__ void init_kernel(const int* __restrict__ ids, int* __restrict__ rowids,
                            __nv_bfloat16* __restrict__ hhi,
                            __nv_bfloat16* __restrict__ hlo)
{
    int t = blockIdx.x * blockDim.x + threadIdx.x;
    if (t == 0) g_arrive = 0u;
    if (t < S * B) {
        int s = t >> 5;
        int b = t & 31;
        rowids[t] = ids[b * S + s];
    }
    if (t < BH) {
        hhi[t] = __float2bfloat16(0.f);
        hlo[t] = __float2bfloat16(0.f);
    }
}

__global__ void wsplit_kernel(const float* __restrict__ w,
                              __nv_bfloat16* __restrict__ hi,
                              __nv_bfloat16* __restrict__ lo, int n)
{
    int i = blockIdx.x * blockDim.x + threadIdx.x;
    if (i < n) {
        float v = w[i];
        __nv_bfloat16 h = __float2bfloat16(v);
        hi[i] = h;
        lo[i] = __float2bfloat16(v - __bfloat162float(h));
    }
}

// ---------------------------------------------------------------------------
// mma / ldmatrix helpers
// ---------------------------------------------------------------------------
__device__ __forceinline__ unsigned f2tf(float f) {
    unsigned r;
    asm("cvt.rna.tf32.f32 %0, %1;" : "=r"(r) : "f"(f));
    return r;
}

#define MMA_TF32(d, a, b)                                                     \
    asm volatile(                                                             \
        "mma.sync.aligned.m16n8k8.row.col.f32.tf32.tf32.f32 "                 \
        "{%0,%1,%2,%3}, {%4,%5,%6,%7}, {%8,%9}, {%0,%1,%2,%3};\n"             \
        : "+f"(d[0]), "+f"(d[1]), "+f"(d[2]), "+f"(d[3])                      \
        : "r"(a[0]), "r"(a[1]), "r"(a[2]), "r"(a[3]), "r"(b[0]), "r"(b[1]))

#define MMA_BF16(d, a, b)                                                     \
    asm volatile(                                                             \
        "mma.sync.aligned.m16n8k16.row.col.f32.bf16.bf16.f32 "                \
        "{%0,%1,%2,%3}, {%4,%5,%6,%7}, {%8,%9}, {%0,%1,%2,%3};\n"             \
        : "+f"(d[0]), "+f"(d[1]), "+f"(d[2]), "+f"(d[3])                      \
        : "r"(a[0]), "r"(a[1]), "r"(a[2]), "r"(a[3]), "r"(b[0]), "r"(b[1]))

#define LDSM_X4T(r, addr)                                                     \
    asm volatile("ldmatrix.sync.aligned.m8n8.x4.trans.shared.b16 {%0,%1,%2,%3},[%4];" \
        : "=r"((r)[0]), "=r"((r)[1]), "=r"((r)[2]), "=r"((r)[3]) : "r"(addr))

#define LDSM_X2(r, addr)                                                      \
    asm volatile("ldmatrix.sync.aligned.m8n8.x2.shared.b16 {%0,%1},[%2];"     \
        : "=r"((r)[0]), "=r"((r)[1]) : "r"(addr))

#define BAR_HALF(id)                                                          \
    asm volatile("bar.sync %0, 256;" :: "r"(id) : "memory")

// ---------------------------------------------------------------------------
// tf32 tensor-core GEMM, A row-major (+gather): C = A[row(m)] . Bm^T (+biases)
// ---------------------------------------------------------------------------
__global__ __launch_bounds__(256)
void gemm_tf32(const float* __restrict__ A, const float* __restrict__ Bm,
               const float* __restrict__ bias1, const float* __restrict__ bias2,
               float* __restrict__ C,
               int M, int N, int K,
               const int* __restrict__ arow)
{
    __shared__ unsigned As[128][20];
    __shared__ unsigned Bs[128][20];

    const int bm = blockIdx.y * 128;
    const int bn = blockIdx.x * 128;
    const int t    = threadIdx.x;
    const int lane = t & 31;
    const int w    = t >> 5;
    const int wm   = (w >> 2) * 64;
    const int wn   = (w & 3) * 32;
    const int gid  = lane >> 2;
    const int tk   = lane & 3;

    const int r0 = t >> 2;
    const int r1 = r0 + 64;
    const int kq = (t & 3) * 4;

    long ar0 = arow ? (long)arow[bm + r0] : (long)(bm + r0);
    long ar1 = arow ? (long)arow[bm + r1] : (long)(bm + r1);
    const float* Ap0 = A + ar0 * K + kq;
    const float* Ap1 = A + ar1 * K + kq;
    const float* Bp0 = Bm + (long)(bn + r0) * K + kq;
    const float* Bp1 = Bm + (long)(bn + r1) * K + kq;

    float acc[4][4][4];
    #pragma unroll
    for (int i = 0; i < 4; i++)
        #pragma unroll
        for (int j = 0; j < 4; j++)
            #pragma unroll
            for (int q = 0; q < 4; q++) acc[i][j][q] = 0.f;

    for (int k0 = 0; k0 < K; k0 += 16) {
        float4 va0 = *(const float4*)(Ap0 + k0);
        float4 va1 = *(const float4*)(Ap1 + k0);
        float4 vb0 = *(const float4*)(Bp0 + k0);
        float4 vb1 = *(const float4*)(Bp1 + k0);

        uint4 pa0 = make_uint4(f2tf(va0.x), f2tf(va0.y), f2tf(va0.z), f2tf(va0.w));
        uint4 pa1 = make_uint4(f2tf(va1.x), f2tf(va1.y), f2tf(va1.z), f2tf(va1.w));
        uint4 pb0 = make_uint4(f2tf(vb0.x), f2tf(vb0.y), f2tf(vb0.z), f2tf(vb0.w));
        uint4 pb1 = make_uint4(f2tf(vb1.x), f2tf(vb1.y), f2tf(vb1.z), f2tf(vb1.w));

        *(uint4*)&As[r0][kq] = pa0;
        *(uint4*)&As[r1][kq] = pa1;
        *(uint4*)&Bs[r0][kq] = pb0;
        *(uint4*)&Bs[r1][kq] = pb1;
        __syncthreads();

        #pragma unroll
        for (int ks = 0; ks < 16; ks += 8) {
            unsigned af[4][4], bf[4][2];
            #pragma unroll
            for (int i = 0; i < 4; i++) {
                int rb = wm + i * 16 + gid;
                af[i][0] = As[rb][ks + tk];
                af[i][1] = As[rb + 8][ks + tk];
                af[i][2] = As[rb][ks + tk + 4];
                af[i][3] = As[rb + 8][ks + tk + 4];
            }
            #pragma unroll
            for (int j = 0; j < 4; j++) {
                int nb = wn + j * 8 + gid;
                bf[j][0] = Bs[nb][ks + tk];
                bf[j][1] = Bs[nb][ks + tk + 4];
            }
            #pragma unroll
            for (int i = 0; i < 4; i++)
                #pragma unroll
                for (int j = 0; j < 4; j++)
                    MMA_TF32(acc[i][j], af[i], bf[j]);
        }
        __syncthreads();
    }

    #pragma unroll
    for (int i = 0; i < 4; i++) {
        int row = bm + wm + i * 16 + gid;
        #pragma unroll
        for (int j = 0; j < 4; j++) {
            int col = bn + wn + j * 8 + tk * 2;
            float b0v = 0.f, b1v = 0.f;
            if (bias1) { b0v += bias1[col]; b1v += bias1[col + 1]; }
            if (bias2) { b0v += bias2[col]; b1v += bias2[col + 1]; }
            float2 v0 = make_float2(acc[i][j][0] + b0v, acc[i][j][1] + b1v);
            float2 v1 = make_float2(acc[i][j][2] + b0v, acc[i][j][3] + b1v);
            *(float2*)&C[(long)row * N + col]       = v0;
            *(float2*)&C[(long)(row + 8) * N + col] = v1;
        }
    }
}

// ---------------------------------------------------------------------------
// tf32 GEMM, A COL-MAJOR ([K][M]) with output-row remap m=s'*B+b -> b*Sact+s'.
// ---------------------------------------------------------------------------
__global__ __launch_bounds__(256)
void gemm_tf32_cm(const float* __restrict__ A, const float* __restrict__ Bm,
                  const float* __restrict__ bias1,
                  float* __restrict__ C,
                  int M, int N, int K, int sact)
{
    __shared__ unsigned As[16][132];
    __shared__ unsigned Bs[128][20];

    const int bm = blockIdx.y * 128;
    const int bn = blockIdx.x * 128;
    const int t    = threadIdx.x;
    const int lane = t & 31;
    const int w    = t >> 5;
    const int wm   = (w >> 2) * 64;
    const int wn   = (w & 3) * 32;
    const int gid  = lane >> 2;
    const int tk   = lane & 3;

    const int akr = t >> 5;            // 0..7
    const int amq = (t & 31) * 4;

    const int r0 = t >> 2;
    const int r1 = r0 + 64;
    const int kq = (t & 3) * 4;
    const float* Bp0 = Bm + (long)(bn + r0) * K + kq;
    const float* Bp1 = Bm + (long)(bn + r1) * K + kq;

    float acc[4][4][4];
    #pragma unroll
    for (int i = 0; i < 4; i++)
        #pragma unroll
        for (int j = 0; j < 4; j++)
            #pragma unroll
            for (int q = 0; q < 4; q++) acc[i][j][q] = 0.f;

    for (int k0 = 0; k0 < K; k0 += 16) {
        #pragma unroll
        for (int p = 0; p < 2; p++) {
            int k = k0 + p * 8 + akr;
            float4 va = *(const float4*)(A + (long)k * M + bm + amq);
            uint4 pa = make_uint4(f2tf(va.x), f2tf(va.y), f2tf(va.z), f2tf(va.w));
            *(uint4*)&As[p * 8 + akr][amq] = pa;
        }
        float4 vb0 = *(const float4*)(Bp0 + k0);
        float4 vb1 = *(const float4*)(Bp1 + k0);
        uint4 pb0 = make_uint4(f2tf(vb0.x), f2tf(vb0.y), f2tf(vb0.z), f2tf(vb0.w));
        uint4 pb1 = make_uint4(f2tf(vb1.x), f2tf(vb1.y), f2tf(vb1.z), f2tf(vb1.w));
        *(uint4*)&Bs[r0][kq] = pb0;
        *(uint4*)&Bs[r1][kq] = pb1;
        __syncthreads();

        #pragma unroll
        for (int ks = 0; ks < 16; ks += 8) {
            unsigned af[4][4], bf[4][2];
            #pragma unroll
            for (int i = 0; i < 4; i++) {
                int rb = wm + i * 16 + gid;
                af[i][0] = As[ks + tk][rb];
                af[i][1] = As[ks + tk][rb + 8];
                af[i][2] = As[ks + tk + 4][rb];
                af[i][3] = As[ks + tk + 4][rb + 8];
            }
            #pragma unroll
            for (int j = 0; j < 4; j++) {
                int nb = wn + j * 8 + gid;
                bf[j][0] = Bs[nb][ks + tk];
                bf[j][1] = Bs[nb][ks + tk + 4];
            }
            #pragma unroll
            for (int i = 0; i < 4; i++)
                #pragma unroll
                for (int j = 0; j < 4; j++)
                    MMA_TF32(acc[i][j], af[i], bf[j]);
        }
        __syncthreads();
    }

    #pragma unroll
    for (int i = 0; i < 4; i++) {
        int mlin0 = bm + wm + i * 16 + gid;     // = s'*B + b
        int row0  = (mlin0 & 31) * sact + (mlin0 >> 5);
        int mlin1 = mlin0 + 8;
        int row1  = (mlin1 & 31) * sact + (mlin1 >> 5);
        #pragma unroll
        for (int j = 0; j < 4; j++) {
            int col = bn + wn + j * 8 + tk * 2;
            float b0v = bias1[col], b1v = bias1[col + 1];
            float2 v0 = make_float2(acc[i][j][0] + b0v, acc[i][j][1] + b1v);
            float2 v1 = make_float2(acc[i][j][2] + b0v, acc[i][j][3] + b1v);
            *(float2*)&C[(long)row0 * N + col] = v0;
            *(float2*)&C[(long)row1 * N + col] = v1;
        }
    }
}

// ---------------------------------------------------------------------------
// Persistent tensor-core LSTM scan — R10: 512 threads, K split across two
// 8-warp halves (named barriers), 4 warps/SMSP for latency hiding; coalesced
// xg staging through smem. W resident in SMEM; red.release grid barrier.
// ---------------------------------------------------------------------------
#define KC 64
#define NCHUNK (H / KC)     // 16
#define HCHUNK (NCHUNK / 2) // 8 per half
#define WPITCH 36
#define PB2 20              // h tile row pitch (words)
#define XPITCH 33           // sxg row pitch (words), conflict-free

#define W_WORDS   (NCHUNK * 32 * WPITCH)            // per split
#define HT_WORDS  (KC * PB2)                        // per h tile buffer
#define SG_WORDS  (4 * 32 * 8)                      // per sgate copy
#define SCAN_SMEM_BYTES ((2 * W_WORDS + 8 * HT_WORDS + 2 * SG_WORDS + 32 * XPITCH) * 4)

__global__ __launch_bounds__(512, 1)
void lstm_scan(const float* __restrict__ xg_base,
               const __nv_bfloat16* __restrict__ whi,
               const __nv_bfloat16* __restrict__ wlo,
               __nv_bfloat16* __restrict__ hhi,   // [2][BH], [n][b]
               __nv_bfloat16* __restrict__ hlo,
               float* __restrict__ hs,            // [n][s'*B+b]
               int ctx, int Sact)
{
    extern __shared__ unsigned sm[];
    unsigned* wh   = sm;                           // [NCHUNK][32][WPITCH]
    unsigned* wl   = wh + W_WORDS;
    unsigned* shh  = wl + W_WORDS;                 // [2 halves][2 bufs][KC][PB2]
    unsigned* shl  = shh + 4 * HT_WORDS;
    float* sgate   = (float*)(shl + 4 * HT_WORDS); // [2 halves][4][32][8]
    float* sxg     = sgate + 2 * SG_WORDS;         // [32][XPITCH]

    const int t    = threadIdx.x;
    const int lane = t & 31;
    const int wid  = t >> 5;           // 0..15
    const int half = t >> 8;           // 0/1 (warps 0-7 / 8-15)
    const int th   = t & 255;          // thread within half
    const int wh8  = wid & 7;          // warp within half
    const int wm   = ((wh8 >> 2) & 1) * 16;
    const int g    = wh8 & 3;
    const int gid  = lane >> 2;
    const int tk   = lane & 3;
    const int n0   = blockIdx.x * 8;
    const int barid = half + 1;

    // ---- W staging: 512 threads, 2 chunks per iteration ----
    {
        const int sr = (t >> 3) & 31;
        const int sq = (t & 7) * 4;
        const int cofs = t >> 8;       // 0/1
        const int wrow = (sr >> 3) * H + n0 + (sr & 7);
        const uint4* gWhi = (const uint4*)(whi + (long)wrow * H) + (t & 7);
        const uint4* gWlo = (const uint4*)(wlo + (long)wrow * H) + (t & 7);
        for (int c2 = 0; c2 < NCHUNK; c2 += 2) {
            int cv = c2 + cofs;
            *(uint4*)&wh[(cv * 32 + sr) * WPITCH + sq] = gWhi[cv * 8];
            *(uint4*)&wl[(cv * 32 + sr) * WPITCH + sq] = gWlo[cv * 8];
        }
    }

    // ---- per-half h staging mapping ----
    const int kl  = th >> 2;           // 0..63
    const int bq4 = th & 3;
    const unsigned h_sw = (unsigned)(kl * PB2 + bq4 * 4);
    unsigned* myshh = shh + half * 2 * HT_WORDS;
    unsigned* myshl = shl + half * 2 * HT_WORDS;

    // ---- frag addressing ----
    const int a_kr = (lane & 7) + ((lane >> 4) & 1) * 8;
    const int a_mc = wm + ((lane >> 3) & 1) * 8;
    const unsigned a_off = (unsigned)(a_kr * (PB2 * 4) + a_mc * 2);
    const int b_row = g * 8 + (lane & 7);
    const int b_kh  = ((lane >> 3) & 1) * 4;
    const unsigned b_off = (unsigned)(b_row * WPITCH + b_kh) * 4;
    const unsigned HTILE_B = HT_WORDS * 4;
    const unsigned WTILE_B = 32 * WPITCH * 4;

    const unsigned myshh_base = (unsigned)__cvta_generic_to_shared(myshh);
    const unsigned myshl_base = (unsigned)__cvta_generic_to_shared(myshl);
    const unsigned wh_base    = (unsigned)__cvta_generic_to_shared(wh);
    const unsigned wl_base    = (unsigned)__cvta_generic_to_shared(wl);

    // pointwise identity (threads 0-255)
    const int b = t & 31;
    const int j = (t >> 5) & 7;
    const int n = n0 + j;
    float cval  = 0.f;

    // xg staging identity (half 1)
    const int xb = th >> 3;            // 0..31
    const int xg4 = (th & 7) >> 1;     // gate 0..3
    const int xq = th & 1;             // quad 0/1

    __syncthreads();

    for (int s = 0; s < S; s++) {
        const int pi = s & 1;
        // half h source: chunks [half*8, half*8+8)
        const uint4* gHhi = (const uint4*)(hhi + (size_t)pi * BH)
                          + (size_t)(half * HCHUNK) * 256 + kl * 4 + bq4;
        const uint4* gHlo = (const uint4*)(hlo + (size_t)pi * BH)
                          + (size_t)(half * HCHUNK) * 256 + kl * 4 + bq4;

        // xg staging (half 1): coalesced uint4 -> sxg
        if (half == 1) {
            const float* xp = xg_base + (size_t)s * (B * G)
                            + (size_t)xb * G + xg4 * H + n0 + xq * 4;
            float4 xv = __ldg((const float4*)xp);
            float* dst = &sxg[xb * XPITCH + xg4 * 8 + xq * 4];
            dst[0] = xv.x; dst[1] = xv.y; dst[2] = xv.z; dst[3] = xv.w;
        }

        // prefetch chunks 0,1 of my half
        uint4 rh[2], rl[2];
        rh[0] = __ldcg(gHhi);       rl[0] = __ldcg(gHlo);
        rh[1] = __ldcg(gHhi + 256); rl[1] = __ldcg(gHlo + 256);

        float aH[4] = {0.f,0.f,0.f,0.f};
        float aL[4] = {0.f,0.f,0.f,0.f};
        float aM[4] = {0.f,0.f,0.f,0.f};

        #pragma unroll
        for (int ch = 0; ch < HCHUNK; ch++) {
            const int buf = ch & 1;
            const int chg = half * HCHUNK + ch;
            *(uint4*)&myshh[buf * HT_WORDS + h_sw] = rh[buf];
            *(uint4*)&myshl[buf * HT_WORDS + h_sw] = rl[buf];
            BAR_HALF(barid);

            if (ch + 2 < HCHUNK) {
                rh[buf] = __ldcg(gHhi + (ch + 2) * 256);
                rl[buf] = __ldcg(gHlo + (ch + 2) * 256);
            }

            const unsigned sha = myshh_base + buf * HTILE_B + a_off;
            const unsigned sla = myshl_base + buf * HTILE_B + a_off;
            const unsigned whb = wh_base + chg * WTILE_B + b_off;
            const unsigned wlb = wl_base + chg * WTILE_B + b_off;

            #pragma unroll
            for (int ks = 0; ks < 4; ks++) {
                unsigned Ahi[4], Alo[4], Bhi[2], Blo[2];
                LDSM_X4T(Ahi, sha + ks * (16 * PB2 * 4));
                LDSM_X4T(Alo, sla + ks * (16 * PB2 * 4));
                LDSM_X2(Bhi, whb + ks * 32);
                LDSM_X2(Blo, wlb + ks * 32);
                MMA_BF16(aH, Ahi, Bhi);
                MMA_BF16(aL, Alo, Bhi);
                MMA_BF16(aM, Ahi, Blo);
            }
            BAR_HALF(barid);   // frags consumed before next staging overwrite
        }

        float fin[4];
        #pragma unroll
        for (int e = 0; e < 4; e++) fin[e] = aH[e] + (aL[e] + aM[e]);

        // partial-gate exchange (each half its own copy)
        float* sg = sgate + half * SG_WORDS;
        sg[(g * 32 + wm + gid) * 8 + 2 * tk]         = fin[0];
        sg[(g * 32 + wm + gid) * 8 + 2 * tk + 1]     = fin[1];
        sg[(g * 32 + wm + gid + 8) * 8 + 2 * tk]     = fin[2];
        sg[(g * 32 + wm + gid + 8) * 8 + 2 * tk + 1] = fin[3];
        __syncthreads();

        if (t < 256) {
            float gi = sgate[(0 * 32 + b) * 8 + j] + sgate[SG_WORDS + (0 * 32 + b) * 8 + j]
                     + sxg[b * XPITCH + 0 * 8 + j];
            float gf = sgate[(1 * 32 + b) * 8 + j] + sgate[SG_WORDS + (1 * 32 + b) * 8 + j]
                     + sxg[b * XPITCH + 1 * 8 + j];
            float gg = sgate[(2 * 32 + b) * 8 + j] + sgate[SG_WORDS + (2 * 32 + b) * 8 + j]
                     + sxg[b * XPITCH + 2 * 8 + j];
            float go = sgate[(3 * 32 + b) * 8 + j] + sgate[SG_WORDS + (3 * 32 + b) * 8 + j]
                     + sxg[b * XPITCH + 3 * 8 + j];

            float iv = 1.f / (1.f + __expf(-gi));
            float fv = 1.f / (1.f + __expf(-gf));
            float gv = tanhf(gg);
            float ov = 1.f / (1.f + __expf(-go));

            cval = fv * cval + iv * gv;
            float hv = ov * tanhf(cval);

            const int po = (s + 1) & 1;
            const int hidx = n * B + b;
            __nv_bfloat16 hb = __float2bfloat16(hv);
            hhi[(size_t)po * BH + hidx] = hb;
            hlo[(size_t)po * BH + hidx] = __float2bfloat16(hv - __bfloat162float(hb));
            if (s >= ctx)
                hs[(long)n * (Sact * B) + (s - ctx) * B + b] = hv;
        }

        if (s == S - 1) break;

        // grid barrier
        __syncthreads();
        if (t == 0) {
            asm volatile("red.release.gpu.global.add.u32 [%0], %1;"
                         :: "l"(&g_arrive), "r"(1u) : "memory");
            const unsigned bound = (unsigned)NB * (unsigned)(s + 1);
            unsigned v;
            do {
                asm volatile("ld.acquire.gpu.global.u32 %0, [%1];"
                             : "=r"(v) : "l"(&g_arrive) : "memory");
            } while (v < bound);
        }
        __syncthreads();
    }
}

// ---------------------------------------------------------------------------
// Launch
// ---------------------------------------------------------------------------
extern "C" void kernel_launch(void* const* d_in, const int* in_sizes, int n_in,
                              void* d_out, int out_size)
{
    const int*   ids   = (const int*)  d_in[0];
    const float* emb   = (const float*)d_in[1];
    const float* w_ih  = (const float*)d_in[2];
    const float* w_hh  = (const float*)d_in[3];
    const float* b_ih  = (const float*)d_in[4];
    const float* b_hh  = (const float*)d_in[5];
    const float* w_out = (const float*)d_in[6];
    const float* b_out = (const float*)d_in[7];

    int ctx  = S - (int)((long)out_size / ((long)B * V));   // = 40
    int Sact = S - ctx;                                     // = 88

    float* xg;   cudaGetSymbolAddress((void**)&xg,   d_xg);
    float* hs;   cudaGetSymbolAddress((void**)&hs,   d_hs);
    int* rowids; cudaGetSymbolAddress((void**)&rowids, d_rowids);
    __nv_bfloat16* whi; cudaGetSymbolAddress((void**)&whi, d_whi);
    __nv_bfloat16* wlo; cudaGetSymbolAddress((void**)&wlo, d_wlo);
    __nv_bfloat16* hhi; cudaGetSymbolAddress((void**)&hhi, d_hhi);
    __nv_bfloat16* hlo; cudaGetSymbolAddress((void**)&hlo, d_hlo);

    static bool attr_set = false;
    if (!attr_set) {
        cudaFuncSetAttribute(lstm_scan, cudaFuncAttributeMaxDynamicSharedMemorySize,
                             SCAN_SMEM_BYTES);
        attr_set = true;
    }

    // 1) init + weight split
    init_kernel<<<(BH + 255) / 256, 256>>>(ids, rowids, hhi, hlo);
    wsplit_kernel<<<(G * H + 255) / 256, 256>>>(w_hh, whi, wlo, G * H);

    // 2) x_gates (tf32)
    gemm_tf32<<<dim3(G / 128, (S * B) / 128), 256>>>(
        emb, w_ih, b_ih, b_hh, xg, S * B, G, I_DIM, rowids);

    // 3) persistent scan
    lstm_scan<<<NB, 512, SCAN_SMEM_BYTES>>>(xg, whi, wlo, hhi, hlo, hs, ctx, Sact);

    // 4) logits (tf32, col-major A + row remap)
    gemm_tf32_cm<<<dim3(V / 128, (B * Sact) / 128), 256>>>(
        hs, w_out, b_out, (float*)d_out, B * Sact, V, H, Sact);
}